// round 6
// baseline (speedup 1.0000x reference)
#include <cuda_runtime.h>

// Problem constants (fixed by setup_inputs): B=8, N=20, K=5, Q=15, D=1024
#define BB     8
#define NN     20
#define KSUP   5
#define QQ     15
#define DD     1024
#define DH     512                // D-half per block
#define ROWS   (KSUP + QQ)        // 20 rows per (b,n)
#define NQ     (NN * QQ)          // 300 queries per batch
#define NQTOT  (BB * NQ)          // 2400 queries total
#define WARPS  16
#define THREADS 512
#define GRID   (2 * NQTOT / WARPS)  // 300 blocks: 150 query-blocks x 2 D-halves

// Scratch (device globals — no allocation allowed)
__device__ float g_proto[BB * NN * DD];      // 640 KB, L2-resident
__device__ float g_termp[BB * NN];
__device__ float g_part[2 * NQTOT * NN];     // 384 KB partial logits

// ---------------------------------------------------------------------------
// K1: proto[b,n,:] = mean_j support, term_p[b,n] = proto . w0
// ---------------------------------------------------------------------------
__global__ __launch_bounds__(256) void proto_kernel(
    const float* __restrict__ emb, const float* __restrict__ weight)
{
    int bn = blockIdx.x;             // b*20 + n
    int t  = threadIdx.x;            // float4 index 0..255
    const float4* base = reinterpret_cast<const float4*>(emb) + (size_t)bn * ROWS * 256;

    float4 s = base[t];
#pragma unroll
    for (int j = 1; j < KSUP; j++) {
        float4 v = base[j * 256 + t];
        s.x += v.x; s.y += v.y; s.z += v.z; s.w += v.w;
    }
    s.x *= 0.2f; s.y *= 0.2f; s.z *= 0.2f; s.w *= 0.2f;
    reinterpret_cast<float4*>(g_proto)[(size_t)bn * 256 + t] = s;

    float4 w0 = reinterpret_cast<const float4*>(weight)[t];
    float tp = s.x * w0.x + s.y * w0.y + s.z * w0.z + s.w * w0.w;
#pragma unroll
    for (int off = 16; off; off >>= 1) tp += __shfl_xor_sync(0xFFFFFFFFu, tp, off);

    __shared__ float red[8];
    if ((t & 31) == 0) red[t >> 5] = tp;
    __syncthreads();
    if (t == 0) {
        float r = 0.f;
#pragma unroll
        for (int w = 0; w < 8; w++) r += red[w];
        g_termp[bn] = r;
    }
}

// ---------------------------------------------------------------------------
// Main: 300 blocks x 512 threads, TWO blocks per SM (43KB smem, 64 regs) =>
// 32 warps/SM. Block = (query-block of 16, D-half). One query per warp over
// its 512-float D-half; scalar FFMA (abs folds into source modifier).
// n-accumulators in regs, two passes of 10; deferred shfl butterflies.
// Each half writes a partial logit; combine kernel sums (deterministic).
// ---------------------------------------------------------------------------
__global__ __launch_bounds__(THREADS, 2) void relnet_half_kernel(
    const float* __restrict__ emb,
    const float* __restrict__ weight,
    const float* __restrict__ bias)
{
    __shared__ float4 sP4[NN * 128];   // proto tile, this D-half: 40960 B
    __shared__ float4 sW2[128];        // w2 half: 2048 B
    __shared__ float  sTp[NN];

    const int tid   = threadIdx.x;
    const int lane  = tid & 31;
    const int warp  = tid >> 5;
    const int qblk  = blockIdx.x >> 1;     // 0..149
    const int half  = blockIdx.x & 1;      // which D-half

    const int g   = qblk * WARPS + warp;   // global query id 0..2399
    const int bMy = g / NQ;
    const int q   = g - bMy * NQ;
    const int bLo = (qblk * WARPS) / NQ;
    const int bHi = (qblk * WARPS + WARPS - 1) / NQ;

    const float4* emb4 = reinterpret_cast<const float4*>(emb);
    const float4* w14  = reinterpret_cast<const float4*>(weight) + 1 * 256 + half * 128;
    const float4* w24  = reinterpret_cast<const float4*>(weight) + 2 * 256 + half * 128;
    const float4* w34  = reinterpret_cast<const float4*>(weight) + 3 * 256 + half * 128;
    const float4* gP4  = reinterpret_cast<const float4*>(g_proto);
    const float bi = bias[0];

    // ---- load this warp's query D-half into registers: q and q*w3 ----
    const int qrow = (bMy * NN + q / QQ) * ROWS + KSUP + q % QQ;
    const float4* r = emb4 + (size_t)qrow * 256 + half * 128;

    float qv[16], cv[16];
    float tq = 0.f;
#pragma unroll
    for (int i = 0; i < 4; i++) {
        const int idx = i * 32 + lane;
        float4 a  = r[idx];
        float4 w3 = w34[idx];
        float4 w1 = w14[idx];
        qv[4*i+0] = a.x; qv[4*i+1] = a.y; qv[4*i+2] = a.z; qv[4*i+3] = a.w;
        cv[4*i+0] = a.x * w3.x; cv[4*i+1] = a.y * w3.y;
        cv[4*i+2] = a.z * w3.z; cv[4*i+3] = a.w * w3.w;
        tq = fmaf(a.x, w1.x, tq); tq = fmaf(a.y, w1.y, tq);
        tq = fmaf(a.z, w1.z, tq); tq = fmaf(a.w, w1.w, tq);
    }
#pragma unroll
    for (int off = 16; off; off >>= 1) tq += __shfl_xor_sync(0xFFFFFFFFu, tq, off);

    float* po = g_part + (size_t)half * NQTOT * NN + (size_t)g * NN;

#pragma unroll 1
    for (int b = bLo; b <= bHi; b++) {
        __syncthreads();   // protect smem from previous iteration's readers
        {
            const float4* src = gP4 + (size_t)b * NN * 256 + half * 128;
            for (int idx = tid; idx < NN * 128; idx += THREADS)
                sP4[idx] = src[(idx >> 7) * 256 + (idx & 127)];
        }
        if (tid < 128) sW2[tid] = w24[tid];
        if (tid < NN)  sTp[tid] = g_termp[b * NN + tid];
        __syncthreads();
        if (bMy != b) continue;

#pragma unroll 1
        for (int pass = 0; pass < 2; pass++) {
            float acc[10];
#pragma unroll
            for (int n = 0; n < 10; n++) acc[n] = 0.f;

            const float4* pb = sP4 + pass * 10 * 128 + lane;
#pragma unroll
            for (int i = 0; i < 4; i++) {
                const float4 w2 = sW2[i * 32 + lane];
#pragma unroll
                for (int n = 0; n < 10; n++) {
                    const float4 p = pb[n * 128 + i * 32];
                    acc[n] = fmaf(fabsf(p.x - qv[4*i+0]), w2.x, acc[n]);
                    acc[n] = fmaf(p.x, cv[4*i+0], acc[n]);
                    acc[n] = fmaf(fabsf(p.y - qv[4*i+1]), w2.y, acc[n]);
                    acc[n] = fmaf(p.y, cv[4*i+1], acc[n]);
                    acc[n] = fmaf(fabsf(p.z - qv[4*i+2]), w2.z, acc[n]);
                    acc[n] = fmaf(p.z, cv[4*i+2], acc[n]);
                    acc[n] = fmaf(fabsf(p.w - qv[4*i+3]), w2.w, acc[n]);
                    acc[n] = fmaf(p.w, cv[4*i+3], acc[n]);
                }
            }

            // deferred reductions: 10 independent butterflies
#pragma unroll
            for (int n = 0; n < 10; n++) {
                float s = acc[n];
#pragma unroll
                for (int off = 16; off; off >>= 1)
                    s += __shfl_xor_sync(0xFFFFFFFFu, s, off);
                acc[n] = s;
            }
            if (lane == 0) {
#pragma unroll
                for (int n = 0; n < 10; n++) {
                    const int nn = pass * 10 + n;
                    // half 0 carries tp + bias; both halves carry their tq part
                    po[nn] = acc[n] + tq + (half == 0 ? sTp[nn] + bi : 0.f);
                }
            }
        }
    }
}

// ---------------------------------------------------------------------------
// K3: out = part[0] + part[1]   (48000 floats, deterministic)
// ---------------------------------------------------------------------------
__global__ __launch_bounds__(512) void combine_kernel(float* __restrict__ out)
{
    int i = blockIdx.x * 512 + threadIdx.x;   // float4 index
    if (i < NQTOT * NN / 4) {
        const float4* p0 = reinterpret_cast<const float4*>(g_part);
        const float4* p1 = reinterpret_cast<const float4*>(g_part + NQTOT * NN);
        float4 a = p0[i], b = p1[i];
        a.x += b.x; a.y += b.y; a.z += b.z; a.w += b.w;
        reinterpret_cast<float4*>(out)[i] = a;
    }
}

// ---------------------------------------------------------------------------
// Launch
// ---------------------------------------------------------------------------
extern "C" void kernel_launch(void* const* d_in, const int* in_sizes, int n_in,
                              void* d_out, int out_size)
{
    const float* emb    = (const float*)d_in[0];
    const float* weight = (const float*)d_in[1];
    const float* bias   = (const float*)d_in[2];
    float* out          = (float*)d_out;

    proto_kernel<<<BB * NN, 256>>>(emb, weight);
    relnet_half_kernel<<<GRID, THREADS>>>(emb, weight, bias);
    combine_kernel<<<(NQTOT * NN / 4 + 511) / 512, 512>>>(out);
}